// round 4
// baseline (speedup 1.0000x reference)
#include <cuda_runtime.h>
#include <cuda_bf16.h>

#define NN   512
#define NCH  20
#define H1   128
#define NB   32
#define NC   16
#define NJH  4          // j-range splits in k2
#define JR   (NN / NJH) // 128 j-rows per CTA
#define LOG2E 1.4426950408889634f

// Scratch (no allocations allowed)
__device__ float g_h[NN * NCH];              // hidden features (512 x 20)
__device__ float g_M[NB * NN * NC];          // M*log2e in [b][i][c] layout
__device__ float g_opart[NJH * NN * NB];     // partial minibatch features

// Packed fp32x2 FMA — native FFMA2 on sm_103a
#define FMA2(d, a, b, c) \
    asm("fma.rn.f32x2 %0, %1, %2, %3;" : "=l"(d) : "l"(a), "l"(b), "l"(c))

// ---------------------------------------------------------------------------
// K1: MLP + projection. 128 CTAs x 128 threads, 4 rows per CTA.
// ---------------------------------------------------------------------------
__global__ void __launch_bounds__(128) k1_mlp_proj(
    const float* __restrict__ x,  const float* __restrict__ W1,
    const float* __restrict__ b1, const float* __restrict__ W2,
    const float* __restrict__ b2, const float* __restrict__ T)
{
    const int i0 = blockIdx.x * 4;
    const int t  = threadIdx.x;

    __shared__ float xs[4][NCH];
    __shared__ float h1s[4][H1];
    __shared__ float hs[4][NCH];
    __shared__ float W2s[H1 * NCH];   // 10 KB

    // cooperative W2 stage (640 float4, coalesced)
    {
        const float4* src = reinterpret_cast<const float4*>(W2);
        float4*       dst = reinterpret_cast<float4*>(W2s);
#pragma unroll
        for (int k = t; k < H1 * NCH / 4; k += 128) dst[k] = src[k];
    }
    if (t < 4 * NCH) xs[t / NCH][t % NCH] = x[i0 * NCH + t];
    __syncthreads();

    // fc1 + relu: thread c handles column c for all 4 rows
    {
        const int c = t;
        float w1c;
        float a0 = b1[c], a1 = a0, a2 = a0, a3 = a0;
#pragma unroll
        for (int k = 0; k < NCH; ++k) {
            w1c = W1[k * H1 + c];
            a0 = fmaf(xs[0][k], w1c, a0);
            a1 = fmaf(xs[1][k], w1c, a1);
            a2 = fmaf(xs[2][k], w1c, a2);
            a3 = fmaf(xs[3][k], w1c, a3);
        }
        h1s[0][c] = fmaxf(a0, 0.f);
        h1s[1][c] = fmaxf(a1, 0.f);
        h1s[2][c] = fmaxf(a2, 0.f);
        h1s[3][c] = fmaxf(a3, 0.f);
    }
    __syncthreads();

    // fc2 + relu: 80 outputs (r, c), weights from smem
    if (t < 4 * NCH) {
        const int r = t / NCH, c = t % NCH;
        float a0 = b2[c], a1 = 0.f, a2 = 0.f, a3 = 0.f;
#pragma unroll 8
        for (int k = 0; k < H1; k += 4) {
            a0 = fmaf(h1s[r][k + 0], W2s[(k + 0) * NCH + c], a0);
            a1 = fmaf(h1s[r][k + 1], W2s[(k + 1) * NCH + c], a1);
            a2 = fmaf(h1s[r][k + 2], W2s[(k + 2) * NCH + c], a2);
            a3 = fmaf(h1s[r][k + 3], W2s[(k + 3) * NCH + c], a3);
        }
        float a = fmaxf((a0 + a1) + (a2 + a3), 0.f);
        hs[r][c] = a;
        g_h[(i0 + r) * NCH + c] = a;
    }
    __syncthreads();

    // proj: M = (h @ T) * log2e, layout [b][i][c]; 4 cols x 4 rows per thread
#pragma unroll
    for (int g2 = 0; g2 < 4; ++g2) {
        const int col = t + g2 * 128;
        const int b = col >> 4, cc = col & 15;
        float m0 = 0.f, m1 = 0.f, m2 = 0.f, m3 = 0.f;
#pragma unroll
        for (int k = 0; k < NCH; ++k) {
            const float tc = T[k * NN + col];
            m0 = fmaf(hs[0][k], tc, m0);
            m1 = fmaf(hs[1][k], tc, m1);
            m2 = fmaf(hs[2][k], tc, m2);
            m3 = fmaf(hs[3][k], tc, m3);
        }
        g_M[(b * NN + (i0 + 0)) * NC + cc] = m0 * LOG2E;
        g_M[(b * NN + (i0 + 1)) * NC + cc] = m1 * LOG2E;
        g_M[(b * NN + (i0 + 2)) * NC + cc] = m2 * LOG2E;
        g_M[(b * NN + (i0 + 3)) * NC + cc] = m3 * LOG2E;
    }
}

// ---------------------------------------------------------------------------
// K2: pairwise L1 + exp2 using native packed FFMA2.
// grid = (32 b, 4 i-chunks, 4 j-ranges) = 512 CTAs, block = 128.
// ---------------------------------------------------------------------------
__global__ void __launch_bounds__(128) k2_pairwise()
{
    const int b  = blockIdx.x;
    const int ic = blockIdx.y;
    const int jh = blockIdx.z;
    const int t  = threadIdx.x;

    __shared__ float Mb[JR * NC];   // 8 KB

    {   // stage j-range (coalesced float4)
        const float4* src = reinterpret_cast<const float4*>(g_M + (b * NN + jh * JR) * NC);
        float4*       dst = reinterpret_cast<float4*>(Mb);
#pragma unroll
        for (int k = t; k < JR * NC / 4; k += 128) dst[k] = src[k];
    }
    __syncthreads();

    const int i = ic * 128 + t;
    unsigned long long mi[8];
    {
        const ulonglong2* gm = reinterpret_cast<const ulonglong2*>(g_M + (b * NN + i) * NC);
#pragma unroll
        for (int k = 0; k < 4; ++k) { ulonglong2 v = gm[k]; mi[2 * k] = v.x; mi[2 * k + 1] = v.y; }
    }

    const unsigned long long NEG1 = 0xBF800000BF800000ULL;  // (-1,-1)
    const unsigned long long ONE  = 0x3F8000003F800000ULL;  // ( 1, 1)
    const unsigned long long ABS2 = 0x7fffffff7fffffffULL;

    float oacc = 0.f;
#pragma unroll 2
    for (int j = 0; j < JR; ++j) {
        const ulonglong2* mj = reinterpret_cast<const ulonglong2*>(Mb + j * NC);
        unsigned long long a[8];
#pragma unroll
        for (int k = 0; k < 4; ++k) {
            ulonglong2 v = mj[k];
            unsigned long long t0, t1;
            FMA2(t0, v.x, NEG1, mi[2 * k]);        // mi - mj   (packed)
            FMA2(t1, v.y, NEG1, mi[2 * k + 1]);
            a[2 * k]     = t0 & ABS2;              // |.| on alu pipe
            a[2 * k + 1] = t1 & ABS2;
        }
        unsigned long long s0, s1, s2, s3;
        FMA2(s0, a[0], ONE, a[1]);  FMA2(s1, a[2], ONE, a[3]);
        FMA2(s2, a[4], ONE, a[5]);  FMA2(s3, a[6], ONE, a[7]);
        FMA2(s0, s0, ONE, s1);      FMA2(s2, s2, ONE, s3);
        FMA2(s0, s0, ONE, s2);
        float lo, hi;
        asm("mov.b64 {%0,%1}, %2;" : "=f"(lo), "=f"(hi) : "l"(s0));
        float nd = -lo - hi;                       // -(d*log2e), M prescaled
        float e;
        asm("ex2.approx.ftz.f32 %0, %1;" : "=f"(e) : "f"(nd));
        oacc += e;
    }
    g_opart[(jh * NN + i) * NB + b] = oacc;
}

// ---------------------------------------------------------------------------
// K3: combine partials, deterministic mean, final linear + sigmoid.
// ---------------------------------------------------------------------------
__global__ void __launch_bounds__(512) k3_head(
    const float* __restrict__ W3, const float* __restrict__ b3,
    float* __restrict__ out)
{
    const int i = threadIdx.x;
    __shared__ float red[NN];

    float orow[NB];
    float s = 0.0f;
#pragma unroll
    for (int b = 0; b < NB; ++b) {
        float v = g_opart[(0 * NN + i) * NB + b]
                + g_opart[(1 * NN + i) * NB + b]
                + g_opart[(2 * NN + i) * NB + b]
                + g_opart[(3 * NN + i) * NB + b];
        orow[b] = v;
        s += v;
    }
    red[i] = s;
    __syncthreads();

#pragma unroll
    for (int st = 256; st > 0; st >>= 1) {
        if (i < st) red[i] += red[i + st];
        __syncthreads();
    }
    const float mean = red[0] * (1.0f / (float)(NN * NB));

    float acc = b3[0];
#pragma unroll
    for (int c = 0; c < NCH; ++c)
        acc = fmaf(g_h[i * NCH + c], W3[c], acc);
#pragma unroll
    for (int b = 0; b < NB; ++b)
        acc = fmaf(orow[b] - mean, W3[NCH + b], acc);

    out[i] = 1.0f / (1.0f + __expf(-acc));
}

// ---------------------------------------------------------------------------
extern "C" void kernel_launch(void* const* d_in, const int* in_sizes, int n_in,
                              void* d_out, int out_size)
{
    const float* x  = (const float*)d_in[0];
    const float* W1 = (const float*)d_in[1];
    const float* b1 = (const float*)d_in[2];
    const float* W2 = (const float*)d_in[3];
    const float* b2 = (const float*)d_in[4];
    const float* T  = (const float*)d_in[5];
    const float* W3 = (const float*)d_in[6];
    const float* b3 = (const float*)d_in[7];
    float* out = (float*)d_out;

    k1_mlp_proj<<<128, 128>>>(x, W1, b1, W2, b2, T);
    dim3 g2(NB, 4, NJH);
    k2_pairwise<<<g2, 128>>>();
    k3_head<<<1, NN>>>(W3, b3, out);
}

// round 5
// speedup vs baseline: 1.8182x; 1.8182x over previous
#include <cuda_runtime.h>
#include <cuda_bf16.h>

#define NN   512
#define NCH  20
#define H1   128
#define NB   32
#define NC   16
#define NJH  4          // j-range splits in k2
#define JR   (NN / NJH) // 128 j-rows per CTA
#define LOG2E 1.4426950408889634f

// Scratch — transposed layouts so every k3 warp-load is 1 cache line
__device__ float g_h[NCH * NN];              // hidden features, [c][i]
__device__ float g_M[NB * NN * NC];          // M*log2e, [b][i][c]
__device__ float g_opart[NJH * NB * NN];     // partials, [jh][b][i]

// Packed fp32x2 FMA — native FFMA2 on sm_103a
#define FMA2(d, a, b, c) \
    asm("fma.rn.f32x2 %0, %1, %2, %3;" : "=l"(d) : "l"(a), "l"(b), "l"(c))

// ---------------------------------------------------------------------------
// K1: MLP + projection. 512 CTAs x 128 threads, ONE row per CTA.
// 13.8 warps/SM — latency of every phase hidden by cross-CTA overlap.
// ---------------------------------------------------------------------------
__global__ void __launch_bounds__(128) k1_mlp_proj(
    const float* __restrict__ x,  const float* __restrict__ W1,
    const float* __restrict__ b1, const float* __restrict__ W2,
    const float* __restrict__ b2, const float* __restrict__ T)
{
    const int i = blockIdx.x;
    const int t = threadIdx.x;

    __shared__ float xs[NCH];
    __shared__ float h1s[H1];
    __shared__ float hs[NCH];
    __shared__ float part[6][NCH + 1];

    if (t < NCH) xs[t] = x[i * NCH + t];
    __syncthreads();

    // fc1 + relu: thread t owns column t
    {
        float a = b1[t];
#pragma unroll
        for (int k = 0; k < NCH; ++k)
            a = fmaf(xs[k], W1[k * H1 + t], a);
        h1s[t] = fmaxf(a, 0.f);
    }
    __syncthreads();

    // fc2: 120 threads = 20 cols x 6 k-slices of 22
    if (t < 120) {
        const int c = t % NCH, q = t / NCH;
        const int k0 = q * 22, k1e = (k0 + 22 < H1) ? k0 + 22 : H1;
        float a = 0.f;
        for (int k = k0; k < k1e; ++k)
            a = fmaf(h1s[k], W2[k * NCH + c], a);
        part[q][c] = a;
    }
    __syncthreads();
    if (t < NCH) {
        float a = b2[t];
#pragma unroll
        for (int q = 0; q < 6; ++q) a += part[q][t];
        a = fmaxf(a, 0.f);
        hs[t] = a;
        g_h[t * NN + i] = a;          // transposed write
    }
    __syncthreads();

    // proj: M = (h @ T) * log2e, 4 cols per thread (coalesced T reads)
    {
        float m0 = 0.f, m1 = 0.f, m2 = 0.f, m3 = 0.f;
#pragma unroll
        for (int k = 0; k < NCH; ++k) {
            const float hk = hs[k];
            const float* Tk = T + k * NN + t;
            m0 = fmaf(hk, Tk[0],   m0);
            m1 = fmaf(hk, Tk[128], m1);
            m2 = fmaf(hk, Tk[256], m2);
            m3 = fmaf(hk, Tk[384], m3);
        }
#pragma unroll
        for (int g = 0; g < 4; ++g) {
            const int col = t + g * 128;
            const float m = (g == 0 ? m0 : g == 1 ? m1 : g == 2 ? m2 : m3);
            g_M[((col >> 4) * NN + i) * NC + (col & 15)] = m * LOG2E;
        }
    }
}

// ---------------------------------------------------------------------------
// K2: pairwise L1 + exp2 using native packed FFMA2.
// grid = (32 b, 4 i-chunks, 4 j-ranges) = 512 CTAs, block = 128.
// ---------------------------------------------------------------------------
__global__ void __launch_bounds__(128) k2_pairwise()
{
    const int b  = blockIdx.x;
    const int ic = blockIdx.y;
    const int jh = blockIdx.z;
    const int t  = threadIdx.x;

    __shared__ float Mb[JR * NC];   // 8 KB

    {   // stage j-range (coalesced float4)
        const float4* src = reinterpret_cast<const float4*>(g_M + (b * NN + jh * JR) * NC);
        float4*       dst = reinterpret_cast<float4*>(Mb);
#pragma unroll
        for (int k = t; k < JR * NC / 4; k += 128) dst[k] = src[k];
    }
    __syncthreads();

    const int i = ic * 128 + t;
    unsigned long long mi[8];
    {
        const ulonglong2* gm = reinterpret_cast<const ulonglong2*>(g_M + (b * NN + i) * NC);
#pragma unroll
        for (int k = 0; k < 4; ++k) { ulonglong2 v = gm[k]; mi[2 * k] = v.x; mi[2 * k + 1] = v.y; }
    }

    const unsigned long long NEG1 = 0xBF800000BF800000ULL;  // (-1,-1)
    const unsigned long long ONE  = 0x3F8000003F800000ULL;  // ( 1, 1)
    const unsigned long long ABS2 = 0x7fffffff7fffffffULL;

    float oacc = 0.f;
#pragma unroll 2
    for (int j = 0; j < JR; ++j) {
        const ulonglong2* mj = reinterpret_cast<const ulonglong2*>(Mb + j * NC);
        unsigned long long a[8];
#pragma unroll
        for (int k = 0; k < 4; ++k) {
            ulonglong2 v = mj[k];
            unsigned long long t0, t1;
            FMA2(t0, v.x, NEG1, mi[2 * k]);        // mi - mj   (packed)
            FMA2(t1, v.y, NEG1, mi[2 * k + 1]);
            a[2 * k]     = t0 & ABS2;              // |.| on alu pipe
            a[2 * k + 1] = t1 & ABS2;
        }
        unsigned long long s0, s1, s2, s3;
        FMA2(s0, a[0], ONE, a[1]);  FMA2(s1, a[2], ONE, a[3]);
        FMA2(s2, a[4], ONE, a[5]);  FMA2(s3, a[6], ONE, a[7]);
        FMA2(s0, s0, ONE, s1);      FMA2(s2, s2, ONE, s3);
        FMA2(s0, s0, ONE, s2);
        float lo, hi;
        asm("mov.b64 {%0,%1}, %2;" : "=f"(lo), "=f"(hi) : "l"(s0));
        float nd = -lo - hi;                       // -(d*log2e), M prescaled
        float e;
        asm("ex2.approx.ftz.f32 %0, %1;" : "=f"(e) : "f"(nd));
        oacc += e;
    }
    g_opart[(jh * NB + b) * NN + i] = oacc;        // transposed, coalesced
}

// ---------------------------------------------------------------------------
// K3: combine partials (coalesced), deterministic mean, final head.
// ---------------------------------------------------------------------------
__global__ void __launch_bounds__(512) k3_head(
    const float* __restrict__ W3, const float* __restrict__ b3,
    float* __restrict__ out)
{
    const int i = threadIdx.x;
    __shared__ float red[NN];

    float orow[NB];
    float s = 0.0f;
#pragma unroll
    for (int b = 0; b < NB; ++b) {
        float v = g_opart[(0 * NB + b) * NN + i]
                + g_opart[(1 * NB + b) * NN + i]
                + g_opart[(2 * NB + b) * NN + i]
                + g_opart[(3 * NB + b) * NN + i];
        orow[b] = v;
        s += v;
    }
    red[i] = s;
    __syncthreads();

#pragma unroll
    for (int st = 256; st > 0; st >>= 1) {
        if (i < st) red[i] += red[i + st];
        __syncthreads();
    }
    const float mean = red[0] * (1.0f / (float)(NN * NB));

    float acc = b3[0];
#pragma unroll
    for (int c = 0; c < NCH; ++c)
        acc = fmaf(g_h[c * NN + i], W3[c], acc);   // coalesced
#pragma unroll
    for (int b = 0; b < NB; ++b)
        acc = fmaf(orow[b] - mean, W3[NCH + b], acc);

    out[i] = 1.0f / (1.0f + __expf(-acc));
}

// ---------------------------------------------------------------------------
extern "C" void kernel_launch(void* const* d_in, const int* in_sizes, int n_in,
                              void* d_out, int out_size)
{
    const float* x  = (const float*)d_in[0];
    const float* W1 = (const float*)d_in[1];
    const float* b1 = (const float*)d_in[2];
    const float* W2 = (const float*)d_in[3];
    const float* b2 = (const float*)d_in[4];
    const float* T  = (const float*)d_in[5];
    const float* W3 = (const float*)d_in[6];
    const float* b3 = (const float*)d_in[7];
    float* out = (float*)d_out;

    k1_mlp_proj<<<NN, 128>>>(x, W1, b1, W2, b2, T);
    dim3 g2(NB, 4, NJH);
    k2_pairwise<<<g2, 128>>>();
    k3_head<<<1, NN>>>(W3, b3, out);
}